// round 7
// baseline (speedup 1.0000x reference)
#include <cuda_runtime.h>
#include <cstdint>

// TropicalLinear forward on GB300:
//   out[n,o] = max_i( x[n,i] + w[o,i] ) + bias[o]
// (the STE soft term cancels exactly in the forward pass)
//
// R4: single FUSED kernel.
//   - split-K max-plus GEMM: 128 CTAs (8 o x 2 n x 8 k), 512 threads,
//     4n x 4o register tile, packed add.rn.f32x2 (x tile duplicated in smem).
//   - grid-wide spin barrier (monotonic ticket epochs, no reset, replay-safe),
//     then each CTA reduces one output row (8 partials + bias) -> d_out.
//   All 128 CTAs are co-resident (128 < 148 SMs, 64KB smem -> occ>=1), so the
//   spin cannot deadlock.

#define N_ROWS  128
#define IN_DIM  1024
#define OUT_DIM 1024
#define SPLIT   8
#define KC      (IN_DIM / SPLIT)   // 128 k per CTA
#define KS      64                 // smem stage depth (2 stages)
#define TN      64
#define TO      128
#define NCTA    128

// 4 MB static scratch for split-K partials (allocation-free rule)
__device__ float        g_part[SPLIT * N_ROWS * OUT_DIM];
__device__ unsigned int g_arrive;   // zero-init; monotonic across launches

__device__ __forceinline__ float neg_inf() { return __int_as_float(0xff800000); }

__device__ __forceinline__ unsigned long long add2(unsigned long long a,
                                                   unsigned long long b) {
    unsigned long long r;
    asm("add.rn.f32x2 %0, %1, %2;" : "=l"(r) : "l"(a), "l"(b));
    return r;
}
__device__ __forceinline__ float lo32(unsigned long long v) {
    return __uint_as_float((unsigned int)v);
}
__device__ __forceinline__ float hi32(unsigned long long v) {
    return __uint_as_float((unsigned int)(v >> 32));
}

extern "C" __global__ void __launch_bounds__(512, 1)
tropical_fused_kernel(const float* __restrict__ x,
                      const float* __restrict__ w,
                      const float* __restrict__ bias,
                      float* __restrict__ out)
{
    // dynamic smem: xs2 [KS][2*TN] (32 KB, x duplicated) + ws [KS][TO] (32 KB)
    extern __shared__ float smem[];
    float* xs2 = smem;                   // KS * 2*TN floats
    float* ws  = smem + KS * 2 * TN;     // KS * TO floats

    const int tid  = threadIdx.x;
    const int tx   = tid & 31;           // o-direction (32 x 4 = 128)
    const int ty   = tid >> 5;           // n-direction (16 x 4 = 64); == warp
    const int warp = ty;
    const int lane = tx;

    const int o0 = blockIdx.x * TO;
    const int n0 = blockIdx.y * TN;
    const int k0 = blockIdx.z * KC;
    const int flat_cta = blockIdx.x + blockIdx.y * 8 + blockIdx.z * 16; // 0..127

    float acc[4][4];
#pragma unroll
    for (int i = 0; i < 4; ++i)
#pragma unroll
        for (int j = 0; j < 4; ++j)
            acc[i][j] = neg_inf();

#pragma unroll
    for (int stage = 0; stage < KC / KS; ++stage) {
        const int kbase = k0 + stage * KS;

        // ---- stage tiles, transposed to k-major; x duplicated (v,v) ----
        // warp owns k-group warp*4 (4 k's); lanes span rows -> STS conflict-free
        {
            const int kk = warp * 4;
            // x tile: 64 rows, duplicated pairs
#pragma unroll
            for (int rr = 0; rr < 2; ++rr) {
                const int row = lane + rr * 32;
                float4 v = *(const float4*)(x + (size_t)(n0 + row) * IN_DIM + kbase + kk);
                *(float2*)&xs2[(kk + 0) * (2 * TN) + 2 * row] = make_float2(v.x, v.x);
                *(float2*)&xs2[(kk + 1) * (2 * TN) + 2 * row] = make_float2(v.y, v.y);
                *(float2*)&xs2[(kk + 2) * (2 * TN) + 2 * row] = make_float2(v.z, v.z);
                *(float2*)&xs2[(kk + 3) * (2 * TN) + 2 * row] = make_float2(v.w, v.w);
            }
            // w tile: 128 rows
#pragma unroll
            for (int rr = 0; rr < 4; ++rr) {
                const int row = lane + rr * 32;
                float4 v = *(const float4*)(w + (size_t)(o0 + row) * IN_DIM + kbase + kk);
                ws[(kk + 0) * TO + row] = v.x;
                ws[(kk + 1) * TO + row] = v.y;
                ws[(kk + 2) * TO + row] = v.z;
                ws[(kk + 3) * TO + row] = v.w;
            }
        }
        __syncthreads();

        // ---- compute: per k = 3 LDS.128 + 8 ADD.F32X2 + 16 FMNMX ----
        // xs2 read is warp-broadcast (all lanes same addr); ws read is 512B
        // contiguous (4 clean phases).
#pragma unroll 4
        for (int k = 0; k < KS; ++k) {
            const ulonglong2 xa = *(const ulonglong2*)&xs2[k * (2 * TN) + ty * 8];
            const ulonglong2 xb = *(const ulonglong2*)&xs2[k * (2 * TN) + ty * 8 + 4];
            const ulonglong2 wv = *(const ulonglong2*)&ws[k * TO + tx * 4];
            unsigned long long xd[4] = {xa.x, xa.y, xb.x, xb.y};
            unsigned long long wp[2] = {wv.x, wv.y};
#pragma unroll
            for (int i = 0; i < 4; ++i) {
#pragma unroll
                for (int jp = 0; jp < 2; ++jp) {
                    unsigned long long s = add2(xd[i], wp[jp]);
                    acc[i][jp * 2 + 0] = fmaxf(acc[i][jp * 2 + 0], lo32(s));
                    acc[i][jp * 2 + 1] = fmaxf(acc[i][jp * 2 + 1], hi32(s));
                }
            }
        }
        __syncthreads();
    }

    // ---- write partial maxes (coalesced) ----
    float* pbase = g_part + (size_t)blockIdx.z * (N_ROWS * OUT_DIM);
#pragma unroll
    for (int i = 0; i < 4; ++i) {
        const int row = n0 + ty * 4 + i;
        float4 a = make_float4(acc[i][0], acc[i][1], acc[i][2], acc[i][3]);
        *(float4*)(pbase + (size_t)row * OUT_DIM + o0 + tx * 4) = a;
    }

    // ---- grid-wide barrier: monotonic ticket epochs (replay-safe, no reset) ----
    __threadfence();      // partials visible gpu-wide before our arrival
    __syncthreads();      // all threads of CTA fenced before tid0 arrives
    if (tid == 0) {
        unsigned int ticket = atomicAdd(&g_arrive, 1u) + 1u;
        unsigned int target = ((ticket + NCTA - 1u) / NCTA) * NCTA; // end of this launch's block
        unsigned int v;
        do {
            asm volatile("ld.acquire.gpu.u32 %0, [%1];"
                         : "=r"(v) : "l"(&g_arrive) : "memory");
        } while (v < target);
    }
    __syncthreads();

    // ---- fused combine: CTA `flat_cta` reduces output row n = flat_cta ----
    if (tid < 256) {
        const int n  = flat_cta;
        const int o4 = tid * 4;                      // o offset, float4 granular
        const float* p = g_part + (size_t)n * OUT_DIM + o4;
        float4 m = make_float4(neg_inf(), neg_inf(), neg_inf(), neg_inf());
#pragma unroll
        for (int s = 0; s < SPLIT; ++s) {
            float4 v = __ldcg((const float4*)(p + (size_t)s * (N_ROWS * OUT_DIM)));
            m.x = fmaxf(m.x, v.x);
            m.y = fmaxf(m.y, v.y);
            m.z = fmaxf(m.z, v.z);
            m.w = fmaxf(m.w, v.w);
        }
        float4 b = *(const float4*)(bias + o4);
        m.x += b.x; m.y += b.y; m.z += b.z; m.w += b.w;
        *(float4*)(out + (size_t)n * OUT_DIM + o4) = m;
    }
}

extern "C" void kernel_launch(void* const* d_in, const int* in_sizes, int n_in,
                              void* d_out, int out_size)
{
    const float* x    = (const float*)d_in[0];   // [128, 1024]
    const float* w    = (const float*)d_in[1];   // [1024, 1024]
    const float* bias = (const float*)d_in[2];   // [1024]
    float* out = (float*)d_out;                  // [128, 1024]

    const int smem_bytes = (KS * 2 * TN + KS * TO) * sizeof(float);  // 64 KB
    static bool attr_set = false;  // idempotent host-side attribute (not a stream op)
    if (!attr_set) {
        cudaFuncSetAttribute(tropical_fused_kernel,
                             cudaFuncAttributeMaxDynamicSharedMemorySize, smem_bytes);
        attr_set = true;
    }

    dim3 grid(OUT_DIM / TO, N_ROWS / TN, SPLIT);  // (8, 2, 8) = 128 CTAs
    tropical_fused_kernel<<<grid, 512, smem_bytes>>>(x, w, bias, out);
}